// round 1
// baseline (speedup 1.0000x reference)
#include <cuda_runtime.h>
#include <cuda_bf16.h>
#include <cstdint>

#define BB 128
#define LL 256
#define HH 1024
#define TT 9

// Scratch (no allocations allowed): emissions + per-batch log-likelihood
__device__ __align__(16) float g_emis[BB * LL * TT];
__device__ float g_llh[BB];

// ---------------------------------------------------------------------------
// Kernel 1: emissions[b,l,t] = dot(hidden[b,l,:], W[t,:]) + b[t]
// Grid: 1024 blocks x 256 threads. Each block: 8 warps x 4 rows = 32 rows.
// W (9x1024 = 36KB) staged in shared memory. HBM-bound on hidden (134 MB).
// ---------------------------------------------------------------------------
__global__ __launch_bounds__(256) void emis_kernel(
    const float* __restrict__ hidden,
    const float* __restrict__ W,
    const float* __restrict__ bias)
{
    __shared__ __align__(16) float Ws[TT * HH];
    __shared__ float bs[TT];

    int tid = threadIdx.x;
    // cooperative load of W into smem (2304 float4)
    const float4* W4 = reinterpret_cast<const float4*>(W);
    float4* Ws4 = reinterpret_cast<float4*>(Ws);
#pragma unroll
    for (int i = 0; i < (TT * HH / 4 + 255) / 256; i++) {
        int idx = tid + i * 256;
        if (idx < TT * HH / 4) Ws4[idx] = W4[idx];
    }
    if (tid < TT) bs[tid] = bias[tid];
    __syncthreads();

    int warp = tid >> 5;
    int lane = tid & 31;
    int row0 = (blockIdx.x * 8 + warp) * 4;  // 4 consecutive rows per warp

    float acc[4][TT];
#pragma unroll
    for (int m = 0; m < 4; m++)
#pragma unroll
        for (int t = 0; t < TT; t++) acc[m][t] = 0.0f;

#pragma unroll
    for (int i = 0; i < 8; i++) {
        int kk = lane + 32 * i;  // float4 index within 256 per row
        float4 hv[4];
#pragma unroll
        for (int m = 0; m < 4; m++) {
            hv[m] = reinterpret_cast<const float4*>(hidden + (size_t)(row0 + m) * HH)[kk];
        }
#pragma unroll
        for (int t = 0; t < TT; t++) {
            float4 wv = reinterpret_cast<const float4*>(Ws + t * HH)[kk];
#pragma unroll
            for (int m = 0; m < 4; m++) {
                acc[m][t] += hv[m].x * wv.x + hv[m].y * wv.y +
                             hv[m].z * wv.z + hv[m].w * wv.w;
            }
        }
    }

    // butterfly reduce across lanes
#pragma unroll
    for (int off = 16; off > 0; off >>= 1) {
#pragma unroll
        for (int m = 0; m < 4; m++)
#pragma unroll
            for (int t = 0; t < TT; t++)
                acc[m][t] += __shfl_xor_sync(0xffffffffu, acc[m][t], off);
    }

    if (lane == 0) {
#pragma unroll
        for (int m = 0; m < 4; m++) {
#pragma unroll
            for (int t = 0; t < TT; t++)
                g_emis[(size_t)(row0 + m) * TT + t] = acc[m][t] + bs[t];
        }
    }
}

// ---------------------------------------------------------------------------
// Kernel 2: CRF forward per batch. 1 warp per batch (grid 128 x 32).
// Probability-domain scan with precomputed E = exp(trans): per-step critical
// chain = 9-FFMA dot + shfl broadcast. Exact power-of-2 renorm every 8 steps.
// ---------------------------------------------------------------------------
__global__ __launch_bounds__(32) void crf_kernel(
    const float* __restrict__ start_t,
    const float* __restrict__ end_t,
    const float* __restrict__ trans,
    const int*   __restrict__ labels,
    const int*   __restrict__ lengths)
{
    __shared__ __align__(16) float em_s[LL * TT + 32];  // padded for t+1 prefetch
    __shared__ float tr_s[TT * TT];
    __shared__ float st_s[TT];
    __shared__ float en_s[TT];
    __shared__ __align__(16) int lab_s[LL];

    int b = blockIdx.x;
    int lane = threadIdx.x;

    // load emissions row for this batch (2304 floats = 576 float4)
    {
        const float4* src = reinterpret_cast<const float4*>(g_emis + (size_t)b * LL * TT);
        float4* dst = reinterpret_cast<float4*>(em_s);
#pragma unroll
        for (int i = 0; i < 576 / 32; i++) dst[lane + 32 * i] = src[lane + 32 * i];
    }
    {
        const int4* lsrc = reinterpret_cast<const int4*>(labels + (size_t)b * LL);
        int4* ldst = reinterpret_cast<int4*>(lab_s);
#pragma unroll
        for (int i = 0; i < 64 / 32; i++) ldst[lane + 32 * i] = lsrc[lane + 32 * i];
    }
    for (int i = lane; i < TT * TT; i += 32) tr_s[i] = trans[i];
    if (lane < TT) { st_s[lane] = start_t[lane]; en_s[lane] = end_t[lane]; }
    int len = lengths[b];
    __syncwarp();

    // ---- numerator (lane-parallel over time steps) ----
    float num_p = 0.0f;
    for (int t = 1 + lane; t < len; t += 32) {
        int pv = lab_s[t - 1], cu = lab_s[t];
        num_p += tr_s[pv * TT + cu] + em_s[t * TT + cu];
    }
#pragma unroll
    for (int off = 16; off > 0; off >>= 1)
        num_p += __shfl_xor_sync(0xffffffffu, num_p, off);
    int tag0 = lab_s[0];
    float num = num_p + st_s[tag0] + em_s[tag0] + en_s[lab_s[len - 1]];

    // ---- denominator: probability-domain forward scan ----
    int j = (lane < TT) ? lane : (TT - 1);  // lane j owns next-state j

    float Ecol[TT];  // E[i][j] for this lane's column j
#pragma unroll
    for (int i = 0; i < TT; i++) Ecol[i] = __expf(tr_s[i * TT + j]);

    float a[TT];  // alpha, replicated in every lane
#pragma unroll
    for (int i = 0; i < TT; i++) a[i] = __expf(st_s[i] + em_s[i]);

    int esum = 0;  // accumulated power-of-2 renorm exponent
    float u_next = __expf(em_s[TT + j]);  // exp(em[1][j]) (safe even if len==1; padded)

    for (int t = 1; t < len; t++) {
        float u = u_next;
        u_next = __expf(em_s[(t + 1) * TT + j]);  // prefetch next step (padded read)

        // nxt_j = u_j * sum_i a[i] * E[i][j]   (3 accumulator chains)
        float s0 = a[0] * Ecol[0];
        float s1 = a[1] * Ecol[1];
        float s2 = a[2] * Ecol[2];
        s0 += a[3] * Ecol[3];
        s1 += a[4] * Ecol[4];
        s2 += a[5] * Ecol[5];
        s0 += a[6] * Ecol[6];
        s1 += a[7] * Ecol[7];
        s2 += a[8] * Ecol[8];
        float nxt = u * (s0 + (s1 + s2));

        // broadcast new alpha vector to all lanes
#pragma unroll
        for (int i = 0; i < TT; i++) a[i] = __shfl_sync(0xffffffffu, nxt, i);

        // exact power-of-2 renormalization every 8 steps
        if ((t & 7) == 0) {
            int e = (__float_as_int(a[0]) >> 23) & 255;      // biased exponent
            float r = __int_as_float((254 - e) << 23);        // 2^(127 - e)
            esum += e - 127;
#pragma unroll
            for (int i = 0; i < TT; i++) a[i] *= r;
        }
    }

    float tot = 0.0f;
#pragma unroll
    for (int i = 0; i < TT; i++) tot += a[i] * __expf(en_s[i]);
    float denom = __logf(tot) + (float)esum * 0.6931471805599453f;

    if (lane == 0) g_llh[b] = num - denom;
}

// ---------------------------------------------------------------------------
// Kernel 3: out = -mean(llh). Deterministic single-warp reduce.
// ---------------------------------------------------------------------------
__global__ __launch_bounds__(32) void final_kernel(float* __restrict__ out)
{
    int lane = threadIdx.x;
    float v = 0.0f;
#pragma unroll
    for (int i = 0; i < BB / 32; i++) v += g_llh[lane + 32 * i];
#pragma unroll
    for (int off = 16; off > 0; off >>= 1)
        v += __shfl_xor_sync(0xffffffffu, v, off);
    if (lane == 0) out[0] = -v * (1.0f / (float)BB);
}

extern "C" void kernel_launch(void* const* d_in, const int* in_sizes, int n_in,
                              void* d_out, int out_size)
{
    const float* hidden  = (const float*)d_in[0];
    const float* W       = (const float*)d_in[1];
    const float* bias    = (const float*)d_in[2];
    const float* start_t = (const float*)d_in[3];
    const float* end_t   = (const float*)d_in[4];
    const float* trans   = (const float*)d_in[5];
    const int*   labels  = (const int*)d_in[6];
    const int*   lengths = (const int*)d_in[7];
    float* out = (float*)d_out;

    emis_kernel<<<(BB * LL) / 32, 256>>>(hidden, W, bias);
    crf_kernel<<<BB, 32>>>(start_t, end_t, trans, labels, lengths);
    final_kernel<<<1, 32>>>(out);
}

// round 2
// speedup vs baseline: 1.0245x; 1.0245x over previous
#include <cuda_runtime.h>
#include <cuda_bf16.h>
#include <cstdint>

#define BB 128
#define LL 256
#define HH 1024
#define TT 9

#define ROWS_PER_TILE 16          // 8 warps x 2 rows
#define NTILES ((BB * LL) / ROWS_PER_TILE)   // 2048
#define EMIS_GRID 592             // persistent: ~4 blocks/SM x 148 SMs

// Scratch (no allocations allowed)
__device__ __align__(16) float g_emis[BB * LL * TT];
__device__ float g_llh[BB];
__device__ int g_ctr;             // self-resetting finish counter

// ---------------------------------------------------------------------------
// Kernel 1: emissions[b,l,t] = dot(hidden[b,l,:], W[t,:]) + b[t]
// Persistent grid. Each block: 8 warps x 2 rows = 16-row tiles, grid-stride.
// W (36KB) staged in smem once per block. Prefetched double-buffered loads
// for deep MLP. Output staged via smem for coalesced stores.
// ---------------------------------------------------------------------------
__global__ __launch_bounds__(256) void emis_kernel(
    const float* __restrict__ hidden,
    const float* __restrict__ W,
    const float* __restrict__ bias)
{
    __shared__ __align__(16) float Ws[TT * HH];
    __shared__ float bs[TT];
    __shared__ float outbuf[ROWS_PER_TILE * TT];  // 144

    int tid = threadIdx.x;
    // cooperative load of W into smem (2304 float4, 9 per thread)
    {
        const float4* W4 = reinterpret_cast<const float4*>(W);
        float4* Ws4 = reinterpret_cast<float4*>(Ws);
#pragma unroll
        for (int i = 0; i < 9; i++) Ws4[tid + i * 256] = W4[tid + i * 256];
        if (tid < TT) bs[tid] = bias[tid];
    }
    __syncthreads();

    int warp = tid >> 5;
    int lane = tid & 31;
    const float4* Ws4 = reinterpret_cast<const float4*>(Ws);

    for (int tile = blockIdx.x; tile < NTILES; tile += gridDim.x) {
        int row0 = tile * ROWS_PER_TILE + warp * 2;

        const float4* h0 = reinterpret_cast<const float4*>(hidden + (size_t)row0 * HH);
        const float4* h1 = h0 + (HH / 4);

        float acc[2][TT];
#pragma unroll
        for (int m = 0; m < 2; m++)
#pragma unroll
            for (int t = 0; t < TT; t++) acc[m][t] = 0.0f;

        // software pipeline: prefetch next iteration's hidden vectors
        float4 c0 = h0[lane];
        float4 c1 = h1[lane];
#pragma unroll
        for (int i = 0; i < 8; i++) {
            float4 n0, n1;
            if (i < 7) {
                n0 = h0[lane + 32 * (i + 1)];
                n1 = h1[lane + 32 * (i + 1)];
            }
            int kk = lane + 32 * i;
#pragma unroll
            for (int t = 0; t < TT; t++) {
                float4 wv = Ws4[t * (HH / 4) + kk];
                acc[0][t] += c0.x * wv.x + c0.y * wv.y + c0.z * wv.z + c0.w * wv.w;
                acc[1][t] += c1.x * wv.x + c1.y * wv.y + c1.z * wv.z + c1.w * wv.w;
            }
            if (i < 7) { c0 = n0; c1 = n1; }
        }

        // butterfly reduce across lanes
#pragma unroll
        for (int off = 16; off > 0; off >>= 1) {
#pragma unroll
            for (int m = 0; m < 2; m++)
#pragma unroll
                for (int t = 0; t < TT; t++)
                    acc[m][t] += __shfl_xor_sync(0xffffffffu, acc[m][t], off);
        }

        if (lane == 0) {
#pragma unroll
            for (int m = 0; m < 2; m++)
#pragma unroll
                for (int t = 0; t < TT; t++)
                    outbuf[(warp * 2 + m) * TT + t] = acc[m][t] + bs[t];
        }
        __syncthreads();
        // coalesced store: 144 contiguous floats per tile
        if (tid < ROWS_PER_TILE * TT)
            g_emis[(size_t)tile * (ROWS_PER_TILE * TT) + tid] = outbuf[tid];
        __syncthreads();
    }
}

// ---------------------------------------------------------------------------
// Kernel 2: CRF forward per batch (1 warp per batch) + fused final reduce.
// Probability-domain scan with precomputed E = exp(trans); exact power-of-2
// renorm every 8 steps. Last block to finish computes -mean(llh).
// ---------------------------------------------------------------------------
__global__ __launch_bounds__(32) void crf_kernel(
    const float* __restrict__ start_t,
    const float* __restrict__ end_t,
    const float* __restrict__ trans,
    const int*   __restrict__ labels,
    const int*   __restrict__ lengths,
    float* __restrict__ out)
{
    __shared__ __align__(16) float em_s[LL * TT + 32];  // padded for t+1 prefetch
    __shared__ float tr_s[TT * TT];
    __shared__ float st_s[TT];
    __shared__ float en_s[TT];
    __shared__ __align__(16) int lab_s[LL];

    int b = blockIdx.x;
    int lane = threadIdx.x;

    {
        const float4* src = reinterpret_cast<const float4*>(g_emis + (size_t)b * LL * TT);
        float4* dst = reinterpret_cast<float4*>(em_s);
#pragma unroll
        for (int i = 0; i < 576 / 32; i++) dst[lane + 32 * i] = src[lane + 32 * i];
    }
    {
        const int4* lsrc = reinterpret_cast<const int4*>(labels + (size_t)b * LL);
        int4* ldst = reinterpret_cast<int4*>(lab_s);
#pragma unroll
        for (int i = 0; i < 64 / 32; i++) ldst[lane + 32 * i] = lsrc[lane + 32 * i];
    }
    for (int i = lane; i < TT * TT; i += 32) tr_s[i] = trans[i];
    if (lane < TT) { st_s[lane] = start_t[lane]; en_s[lane] = end_t[lane]; }
    int len = lengths[b];
    __syncwarp();

    // ---- numerator (lane-parallel over time steps) ----
    float num_p = 0.0f;
    for (int t = 1 + lane; t < len; t += 32) {
        int pv = lab_s[t - 1], cu = lab_s[t];
        num_p += tr_s[pv * TT + cu] + em_s[t * TT + cu];
    }
#pragma unroll
    for (int off = 16; off > 0; off >>= 1)
        num_p += __shfl_xor_sync(0xffffffffu, num_p, off);
    int tag0 = lab_s[0];
    float num = num_p + st_s[tag0] + em_s[tag0] + en_s[lab_s[len - 1]];

    // ---- denominator: probability-domain forward scan ----
    int j = (lane < TT) ? lane : (TT - 1);  // lane j owns next-state j

    float Ecol[TT];
#pragma unroll
    for (int i = 0; i < TT; i++) Ecol[i] = __expf(tr_s[i * TT + j]);

    float a[TT];
#pragma unroll
    for (int i = 0; i < TT; i++) a[i] = __expf(st_s[i] + em_s[i]);

    int esum = 0;
    float u_next = __expf(em_s[TT + j]);

    for (int t = 1; t < len; t++) {
        float u = u_next;
        u_next = __expf(em_s[(t + 1) * TT + j]);  // padded read OK

        float s0 = a[0] * Ecol[0];
        float s1 = a[1] * Ecol[1];
        float s2 = a[2] * Ecol[2];
        s0 += a[3] * Ecol[3];
        s1 += a[4] * Ecol[4];
        s2 += a[5] * Ecol[5];
        s0 += a[6] * Ecol[6];
        s1 += a[7] * Ecol[7];
        s2 += a[8] * Ecol[8];
        float nxt = u * (s0 + (s1 + s2));

#pragma unroll
        for (int i = 0; i < TT; i++) a[i] = __shfl_sync(0xffffffffu, nxt, i);

        if ((t & 7) == 0) {
            int e = (__float_as_int(a[0]) >> 23) & 255;
            float r = __int_as_float((254 - e) << 23);  // exact 2^(127-e)
            esum += e - 127;
#pragma unroll
            for (int i = 0; i < TT; i++) a[i] *= r;
        }
    }

    float tot = 0.0f;
#pragma unroll
    for (int i = 0; i < TT; i++) tot += a[i] * __expf(en_s[i]);
    float denom = __logf(tot) + (float)esum * 0.6931471805599453f;

    if (lane == 0) g_llh[b] = num - denom;

    // ---- fused finalization: last block computes -mean(llh) ----
    __threadfence();
    __syncwarp();
    int last = 0;
    if (lane == 0) {
        int old = atomicAdd(&g_ctr, 1);
        last = (old == BB - 1);
    }
    last = __shfl_sync(0xffffffffu, last, 0);
    if (last) {
        __threadfence();  // acquire: see all g_llh writes
        float v = 0.0f;
#pragma unroll
        for (int i = 0; i < BB / 32; i++) v += g_llh[lane + 32 * i];
#pragma unroll
        for (int off = 16; off > 0; off >>= 1)
            v += __shfl_xor_sync(0xffffffffu, v, off);
        if (lane == 0) {
            out[0] = -v * (1.0f / (float)BB);
            g_ctr = 0;  // self-reset for next graph replay
        }
    }
}

extern "C" void kernel_launch(void* const* d_in, const int* in_sizes, int n_in,
                              void* d_out, int out_size)
{
    const float* hidden  = (const float*)d_in[0];
    const float* W       = (const float*)d_in[1];
    const float* bias    = (const float*)d_in[2];
    const float* start_t = (const float*)d_in[3];
    const float* end_t   = (const float*)d_in[4];
    const float* trans   = (const float*)d_in[5];
    const int*   labels  = (const int*)d_in[6];
    const int*   lengths = (const int*)d_in[7];
    float* out = (float*)d_out;

    emis_kernel<<<EMIS_GRID, 256>>>(hidden, W, bias);
    crf_kernel<<<BB, 32>>>(start_t, end_t, trans, labels, lengths, out);
}

// round 3
// speedup vs baseline: 1.1573x; 1.1296x over previous
#include <cuda_runtime.h>
#include <cuda_bf16.h>
#include <cstdint>

#define BB 128
#define LL 256
#define HH 1024
#define TT 9
#define CHUNK 32

#define ROWS_PER_TILE 16                      // 8 warps x 2 rows
#define NTILES ((BB * LL) / ROWS_PER_TILE)    // 2048
#define EMIS_GRID 444                         // 148 SMs x 3 blocks

// Scratch (no allocations allowed)
__device__ __align__(16) float g_emis[BB * LL * TT];
__device__ float g_llh[BB];
__device__ int g_ctr;

// Packed f32x2 FMA (Blackwell) — halves FMA instruction count
#define FFMA2(acc, a, b) \
    asm("fma.rn.f32x2 %0, %1, %2, %0;" : "+l"(acc) : "l"(a), "l"(b))

// ---------------------------------------------------------------------------
// Kernel 1: emissions = hidden @ W^T + b.  Persistent grid, 2 rows/warp,
// 3-deep LDG pipeline (6 LDG.128 in flight/warp), packed FFMA2.
// ---------------------------------------------------------------------------
__global__ __launch_bounds__(256, 3) void emis_kernel(
    const float* __restrict__ hidden,
    const float* __restrict__ W,
    const float* __restrict__ bias)
{
    __shared__ __align__(16) float Ws[TT * HH];
    __shared__ float bs[TT];
    __shared__ float outbuf[ROWS_PER_TILE * TT];

    int tid = threadIdx.x;
    {
        const float4* W4 = reinterpret_cast<const float4*>(W);
        float4* Ws4 = reinterpret_cast<float4*>(Ws);
#pragma unroll
        for (int i = 0; i < 9; i++) Ws4[tid + i * 256] = W4[tid + i * 256];
        if (tid < TT) bs[tid] = bias[tid];
    }
    __syncthreads();

    int warp = tid >> 5;
    int lane = tid & 31;
    const ulonglong2* Ws2 = reinterpret_cast<const ulonglong2*>(Ws);

    for (int tile = blockIdx.x; tile < NTILES; tile += gridDim.x) {
        int row0 = tile * ROWS_PER_TILE + warp * 2;
        const ulonglong2* H0 =
            reinterpret_cast<const ulonglong2*>(hidden + (size_t)row0 * HH);
        const ulonglong2* H1 = H0 + (HH / 4);

        unsigned long long acc[2][TT];
#pragma unroll
        for (int m = 0; m < 2; m++)
#pragma unroll
            for (int t = 0; t < TT; t++) acc[m][t] = 0ull;  // {0f,0f}

        // 3-stage rotating prefetch buffers
        ulonglong2 b0[3], b1[3];
#pragma unroll
        for (int s = 0; s < 3; s++) {
            b0[s] = H0[lane + 32 * s];
            b1[s] = H1[lane + 32 * s];
        }

#pragma unroll
        for (int i = 0; i < 8; i++) {
            int slot = i % 3;
            ulonglong2 c0 = b0[slot], c1 = b1[slot];
            if (i < 5) {
                b0[slot] = H0[lane + 32 * (i + 3)];
                b1[slot] = H1[lane + 32 * (i + 3)];
            }
            int kk = lane + 32 * i;
#pragma unroll
            for (int t = 0; t < TT; t++) {
                ulonglong2 wv = Ws2[t * 256 + kk];
                FFMA2(acc[0][t], c0.x, wv.x);
                FFMA2(acc[0][t], c0.y, wv.y);
                FFMA2(acc[1][t], c1.x, wv.x);
                FFMA2(acc[1][t], c1.y, wv.y);
            }
        }

        // unpack packed partial sums
        float r[2][TT];
#pragma unroll
        for (int m = 0; m < 2; m++)
#pragma unroll
            for (int t = 0; t < TT; t++) {
                float lo, hi;
                asm("mov.b64 {%0,%1}, %2;" : "=f"(lo), "=f"(hi) : "l"(acc[m][t]));
                r[m][t] = lo + hi;
            }

#pragma unroll
        for (int off = 16; off > 0; off >>= 1) {
#pragma unroll
            for (int m = 0; m < 2; m++)
#pragma unroll
                for (int t = 0; t < TT; t++)
                    r[m][t] += __shfl_xor_sync(0xffffffffu, r[m][t], off);
        }

        if (lane == 0) {
#pragma unroll
            for (int m = 0; m < 2; m++)
#pragma unroll
                for (int t = 0; t < TT; t++)
                    outbuf[(warp * 2 + m) * TT + t] = r[m][t] + bs[t];
        }
        __syncthreads();
        if (tid < ROWS_PER_TILE * TT)
            g_emis[(size_t)tile * (ROWS_PER_TILE * TT) + tid] = outbuf[tid];
        __syncthreads();
    }
}

// ---------------------------------------------------------------------------
// Kernel 2: chunk-parallel CRF forward. One block (256 thr) per batch.
// Warp w computes P_w = prod_{t in chunk w} (E diag(u_t)) right-to-left:
// lane j owns column j (no cross-lane traffic), E replicated in registers,
// exact power-of-2 per-column renorm every 4 steps. Warp 0 combines the 8
// chunk matrices with integer exponent tracking, adds the numerator, and the
// last block reduces -mean(llh).
// ---------------------------------------------------------------------------
__global__ __launch_bounds__(256) void crf_kernel(
    const float* __restrict__ start_t,
    const float* __restrict__ end_t,
    const float* __restrict__ trans,
    const int*   __restrict__ labels,
    const int*   __restrict__ lengths,
    float* __restrict__ out)
{
    __shared__ __align__(16) float em_s[LL * TT];
    __shared__ float u_s[LL * TT];
    __shared__ float tr_s[TT * TT];
    __shared__ float Etr_s[TT * TT];
    __shared__ float st_s[TT];
    __shared__ float en_s[TT];
    __shared__ __align__(16) int lab_s[LL];
    __shared__ float P_s[8][TT][TT];   // [chunk][k][j]
    __shared__ int   e_s[8][TT];
    __shared__ float num_red[8];

    int b = blockIdx.x;
    int tid = threadIdx.x;
    int lane = tid & 31;
    int w = tid >> 5;

    // ---- phase 0: loads ----
    {
        const float4* src = reinterpret_cast<const float4*>(g_emis + (size_t)b * LL * TT);
        float4* dst = reinterpret_cast<float4*>(em_s);
        for (int i = tid; i < LL * TT / 4; i += 256) dst[i] = src[i];
    }
    if (tid < LL / 4) {
        reinterpret_cast<int4*>(lab_s)[tid] =
            reinterpret_cast<const int4*>(labels + (size_t)b * LL)[tid];
    }
    if (tid < TT * TT) {
        float tv = trans[tid];
        tr_s[tid] = tv;
        Etr_s[tid] = __expf(tv);
    }
    if (tid < TT) { st_s[tid] = start_t[tid]; en_s[tid] = end_t[tid]; }
    int len = lengths[b];
    __syncthreads();

    // ---- phase 1: u = exp(em), numerator partials ----
    for (int i = tid; i < LL * TT; i += 256) u_s[i] = __expf(em_s[i]);

    float num_p = 0.0f;
    for (int t = 1 + tid; t < len; t += 256) {
        int pv = lab_s[t - 1], cu = lab_s[t];
        num_p += tr_s[pv * TT + cu] + em_s[t * TT + cu];
    }
#pragma unroll
    for (int off = 16; off > 0; off >>= 1)
        num_p += __shfl_xor_sync(0xffffffffu, num_p, off);
    if (lane == 0) num_red[w] = num_p;
    __syncthreads();

    // ---- phase 2: chunked matrix scan ----
    int lo = (w == 0) ? 1 : CHUNK * w;
    int hi = min(CHUNK * (w + 1), len);
    int j = (lane < TT) ? lane : (TT - 1);

    float E[TT * TT];
#pragma unroll
    for (int i = 0; i < TT * TT; i++) E[i] = Etr_s[i];

    float P[TT];
#pragma unroll
    for (int k = 0; k < TT; k++) P[k] = (k == j) ? 1.0f : 0.0f;
    int esum = 0;

    for (int t = hi - 1; t >= lo; t--) {
        const float* u = &u_s[t * TT];
        float wv[TT];
#pragma unroll
        for (int k = 0; k < TT; k++) wv[k] = u[k] * P[k];
        float np[TT];
#pragma unroll
        for (int i = 0; i < TT; i++) {
            float s = E[i * TT + 0] * wv[0];
#pragma unroll
            for (int k = 1; k < TT; k++) s += E[i * TT + k] * wv[k];
            np[i] = s;
        }
#pragma unroll
        for (int i = 0; i < TT; i++) P[i] = np[i];

        if (((hi - t) & 3) == 0) {  // every 4 completed steps
            int e = (__float_as_int(P[0]) >> 23) & 255;
            float r = __int_as_float((254 - e) << 23);  // exact 2^(127-e)
            esum += e - 127;
#pragma unroll
            for (int i = 0; i < TT; i++) P[i] *= r;
        }
    }

    if (lane < TT) {
#pragma unroll
        for (int k = 0; k < TT; k++) P_s[w][k][j] = P[k];
        e_s[w][j] = esum;
    }
    __syncthreads();

    // ---- phase 3: combine (warp 0) ----
    if (w == 0) {
        float v[TT];
        int G = 0;
#pragma unroll
        for (int k = 0; k < TT; k++) v[k] = __expf(st_s[k] + em_s[k]);

#pragma unroll
        for (int c = 0; c < 8; c++) {
            float nv[TT];
            int T[TT];
#pragma unroll
            for (int jj = 0; jj < TT; jj++) {
                float s = v[0] * P_s[c][0][jj];
#pragma unroll
                for (int k = 1; k < TT; k++) s += v[k] * P_s[c][k][jj];
                nv[jj] = s;
                T[jj] = G + e_s[c][jj] + ((__float_as_int(s) >> 23) & 255);
            }
            int Tmax = T[0];
#pragma unroll
            for (int jj = 1; jj < TT; jj++) Tmax = max(Tmax, T[jj]);
            int Gnew = Tmax - 127;
#pragma unroll
            for (int jj = 0; jj < TT; jj++) {
                int s2 = G + e_s[c][jj] - Gnew;
                v[jj] = (s2 < -126) ? 0.0f
                                    : nv[jj] * __int_as_float((127 + s2) << 23);
            }
            G = Gnew;
        }

        float tot = 0.0f;
#pragma unroll
        for (int k = 0; k < TT; k++) tot += v[k] * __expf(en_s[k]);
        float denom = __logf(tot) + (float)G * 0.6931471805599453f;

        float ns = (lane < 8) ? num_red[lane] : 0.0f;
#pragma unroll
        for (int off = 4; off > 0; off >>= 1)
            ns += __shfl_xor_sync(0xffffffffu, ns, off);
        ns = __shfl_sync(0xffffffffu, ns, 0);
        int tag0 = lab_s[0];
        float num = ns + st_s[tag0] + em_s[tag0] + en_s[lab_s[len - 1]];

        if (lane == 0) g_llh[b] = num - denom;

        // ---- fused finalization ----
        __threadfence();
        __syncwarp();
        int last = 0;
        if (lane == 0) {
            int old = atomicAdd(&g_ctr, 1);
            last = (old == BB - 1);
        }
        last = __shfl_sync(0xffffffffu, last, 0);
        if (last) {
            __threadfence();
            float vv = 0.0f;
#pragma unroll
            for (int i = 0; i < BB / 32; i++) vv += g_llh[lane + 32 * i];
#pragma unroll
            for (int off = 16; off > 0; off >>= 1)
                vv += __shfl_xor_sync(0xffffffffu, vv, off);
            if (lane == 0) {
                out[0] = -vv * (1.0f / (float)BB);
                g_ctr = 0;  // self-reset for graph replay
            }
        }
    }
}

extern "C" void kernel_launch(void* const* d_in, const int* in_sizes, int n_in,
                              void* d_out, int out_size)
{
    const float* hidden  = (const float*)d_in[0];
    const float* W       = (const float*)d_in[1];
    const float* bias    = (const float*)d_in[2];
    const float* start_t = (const float*)d_in[3];
    const float* end_t   = (const float*)d_in[4];
    const float* trans   = (const float*)d_in[5];
    const int*   labels  = (const int*)d_in[6];
    const int*   lengths = (const int*)d_in[7];
    float* out = (float*)d_out;

    emis_kernel<<<EMIS_GRID, 256>>>(hidden, W, bias);
    crf_kernel<<<BB, 256>>>(start_t, end_t, trans, labels, lengths, out);
}